// round 10
// baseline (speedup 1.0000x reference)
#include <cuda_runtime.h>
#include <cuda_bf16.h>
#include <cstdint>

// ---------------------------------------------------------------------------
// Problem: B=16, S=1024, IN=512, OUT=256.
// out = softmax((x Wq^T)(x Wk^T)^T / sqrt(512)) (x Wv^T)
// RoPE uses ONE fixed rotation per dim-pair applied identically to Q and K;
// 2x2 rotations are orthogonal => (Rq).(Rk) = q.k, and V is unroped, so RoPE
// cancels exactly and is skipped.
//
// GEMM engine: mma.sync.m16n8k16 bf16 (family-portable HMMA; tcgen05 is not
// available because the harness compiles for the sm_103 family target).
// Accuracy: 2-term bf16 split (x = hi + lo): accumulate hh + hl + lh in fp32.
// ---------------------------------------------------------------------------
#define BATCH   16
#define SEQ     1024
#define IN_DIM  512
#define OUT_DIM 256

#define THREADS 256
#define BM 128
#define BN 128
#define BK 16              // fp32 elements per K-chunk

#define ROWB 48            // SMEM row stride bytes (16 bf16 = 32B + 16B pad)
#define TILE_HALF (128 * ROWB)   // one operand, one half (hi or lo): 6144 B

#define SCALE 0.044194173824159216f   // 1/sqrt(512)

// ---------------------------------------------------------------------------
// Scratch (device globals; allocations are forbidden)
// ---------------------------------------------------------------------------
__device__ float g_q [BATCH * SEQ * OUT_DIM];          // [b*S+s][d]
__device__ float g_k [BATCH * SEQ * OUT_DIM];          // [b*S+s][d]
__device__ float g_vt[BATCH * OUT_DIM * SEQ];          // [b][d][s]  (V^T)
__device__ float g_s [(size_t)BATCH * SEQ * SEQ];      // scores/probs in place

// ---------------------------------------------------------------------------
// Helpers
// ---------------------------------------------------------------------------
__device__ __forceinline__ uint32_t smem_u32(const void* p) {
    uint32_t a;
    asm("{ .reg .u64 t; cvta.to.shared.u64 t, %1; cvt.u32.u64 %0, t; }"
        : "=r"(a) : "l"(p));
    return a;
}

#define LDSM4(R, addr) \
    asm volatile("ldmatrix.sync.aligned.m8n8.x4.shared.b16 {%0,%1,%2,%3}, [%4];" \
        : "=r"((R)[0]), "=r"((R)[1]), "=r"((R)[2]), "=r"((R)[3]) : "r"(addr))

#define MMA16816(C, A, B0, B1) \
    asm volatile( \
        "mma.sync.aligned.m16n8k16.row.col.f32.bf16.bf16.f32 " \
        "{%0,%1,%2,%3}, {%4,%5,%6,%7}, {%8,%9}, {%0,%1,%2,%3};" \
        : "+f"((C)[0]), "+f"((C)[1]), "+f"((C)[2]), "+f"((C)[3]) \
        : "r"((A)[0]), "r"((A)[1]), "r"((A)[2]), "r"((A)[3]), \
          "r"(B0), "r"(B1))

// ---------------------------------------------------------------------------
// Core tile GEMM: acc(128x128, fp32) += A[128 x K] @ B[128 x K]^T
// A, B fp32 row-major (K contiguous). Split-bf16 3-pass per chunk.
// Warp layout: 8 warps as 2(M) x 4(N); warp tile 64 x 32.
// acc[mi][ni][r]: mi = m16 tile (0..3), ni = n8 tile (0..3), r = mma C regs.
// ---------------------------------------------------------------------------
__device__ __forceinline__ void gemm_tile(const float* __restrict__ A, int lda,
                                          const float* __restrict__ B, int ldb,
                                          int nchunks, float (&acc)[4][4][4]) {
    __shared__ __align__(16) char smem[4 * TILE_HALF];   // A_hi A_lo B_hi B_lo

    const int tid  = threadIdx.x;
    const int lane = tid & 31;
    const int warp = tid >> 5;
    const int wm = (warp >> 2) * 64;    // warp m origin (0 or 64)
    const int wn = (warp & 3) * 32;     // warp n origin (0,32,64,96)

    const uint32_t sb = smem_u32(smem);

    // ldmatrix addresses.
    // A x4 (one m16 x k16 tile): lanes 0-15 rows m0..m0+15 @byte0,
    //                            lanes 16-31 same rows @byte16.
    uint32_t a_addr[4];
    #pragma unroll
    for (int mi = 0; mi < 4; ++mi)
        a_addr[mi] = sb + (uint32_t)((wm + mi * 16 + (lane & 15)) * ROWB
                                     + (lane >> 4) * 16);
    // B x4 (two n8 tiles x k16): lanes 0-7 n0..n0+7 @byte0, 8-15 same @byte16,
    //                            16-23 n0+8.. @byte0, 24-31 same @byte16.
    uint32_t b_addr[2];
    #pragma unroll
    for (int p = 0; p < 2; ++p)
        b_addr[p] = sb + 2u * TILE_HALF
                  + (uint32_t)((wn + p * 16 + (lane & 7) + ((lane & 16) ? 8 : 0)) * ROWB
                               + ((lane & 8) ? 16 : 0));

    float4 pf[4];  // prefetch regs: pf[0..1] = A float4s, pf[2..3] = B float4s

    // Prologue: load chunk 0.
    #pragma unroll
    for (int i = 0; i < 2; ++i) {
        int idx = tid + i * 256;       // float4 index within 128x16 tile
        int r = idx >> 2, f = idx & 3;
        pf[i]     = *reinterpret_cast<const float4*>(A + (size_t)r * lda + f * 4);
        pf[2 + i] = *reinterpret_cast<const float4*>(B + (size_t)r * ldb + f * 4);
    }

    #pragma unroll 1
    for (int ch = 0; ch < nchunks; ++ch) {
        if (ch > 0) __syncthreads();   // previous chunk's MMAs done

        // Convert prefetch regs -> bf16 hi/lo -> SMEM.
        #pragma unroll
        for (int i = 0; i < 4; ++i) {
            int idx = tid + (i & 1) * 256;
            int r = idx >> 2, f = idx & 3;
            char* dst = smem + (i < 2 ? 0 : 2 * TILE_HALF) + r * ROWB + f * 8;
            float4 v = pf[i];
            __nv_bfloat162 h0 = __floats2bfloat162_rn(v.x, v.y);
            __nv_bfloat162 h1 = __floats2bfloat162_rn(v.z, v.w);
            float2 q0 = __bfloat1622float2(h0);
            float2 q1 = __bfloat1622float2(h1);
            __nv_bfloat162 l0 = __floats2bfloat162_rn(v.x - q0.x, v.y - q0.y);
            __nv_bfloat162 l1 = __floats2bfloat162_rn(v.z - q1.x, v.w - q1.y);
            uint2 hw = make_uint2(*reinterpret_cast<uint32_t*>(&h0),
                                  *reinterpret_cast<uint32_t*>(&h1));
            uint2 lw = make_uint2(*reinterpret_cast<uint32_t*>(&l0),
                                  *reinterpret_cast<uint32_t*>(&l1));
            *reinterpret_cast<uint2*>(dst) = hw;
            *reinterpret_cast<uint2*>(dst + TILE_HALF) = lw;
        }
        __syncthreads();

        // Issue next chunk's LDGs now; they drain while we do MMA.
        if (ch + 1 < nchunks) {
            const float* An = A + (size_t)(ch + 1) * BK;
            const float* Bn = B + (size_t)(ch + 1) * BK;
            #pragma unroll
            for (int i = 0; i < 2; ++i) {
                int idx = tid + i * 256;
                int r = idx >> 2, f = idx & 3;
                pf[i]     = *reinterpret_cast<const float4*>(An + (size_t)r * lda + f * 4);
                pf[2 + i] = *reinterpret_cast<const float4*>(Bn + (size_t)r * ldb + f * 4);
            }
        }

        // Load fragments.
        uint32_t ah[4][4], al[4][4], bh[4][2], bl[4][2];
        #pragma unroll
        for (int mi = 0; mi < 4; ++mi) {
            LDSM4(ah[mi], a_addr[mi]);
            LDSM4(al[mi], a_addr[mi] + TILE_HALF);
        }
        #pragma unroll
        for (int p = 0; p < 2; ++p) {
            uint32_t t[4];
            LDSM4(t, b_addr[p]);
            bh[2*p][0] = t[0]; bh[2*p][1] = t[1];
            bh[2*p+1][0] = t[2]; bh[2*p+1][1] = t[3];
            LDSM4(t, b_addr[p] + TILE_HALF);
            bl[2*p][0] = t[0]; bl[2*p][1] = t[1];
            bl[2*p+1][0] = t[2]; bl[2*p+1][1] = t[3];
        }

        // 3-pass split MMA: hh + hl + lh.
        #pragma unroll
        for (int mi = 0; mi < 4; ++mi)
            #pragma unroll
            for (int ni = 0; ni < 4; ++ni) {
                MMA16816(acc[mi][ni], ah[mi], bh[ni][0], bh[ni][1]);
                MMA16816(acc[mi][ni], ah[mi], bl[ni][0], bl[ni][1]);
                MMA16816(acc[mi][ni], al[mi], bh[ni][0], bh[ni][1]);
            }
    }
}

// Fragment -> (row, col) helpers. C regs: r0,r1 at (row, col..col+1),
// r2,r3 at (row+8, col..col+1).
__device__ __forceinline__ int frag_row(int mi) {
    int lane = threadIdx.x & 31, warp = threadIdx.x >> 5;
    return (warp >> 2) * 64 + mi * 16 + (lane >> 2);
}
__device__ __forceinline__ int frag_col(int ni) {
    int lane = threadIdx.x & 31, warp = threadIdx.x >> 5;
    return (warp & 3) * 32 + ni * 8 + 2 * (lane & 3);
}

// ---------------------------------------------------------------------------
// Kernel 1: fused QKV. A = x[16384,512]; B = W[256,512] (rows = out dim).
// grid (128 mtiles, 2 ntiles, 3 which). which: 0=Q, 1=K, 2=V (stored V^T).
// ---------------------------------------------------------------------------
__global__ void __launch_bounds__(THREADS, 1)
qkv_kernel(const float* __restrict__ x,
           const float* __restrict__ wq, const float* __restrict__ bq,
           const float* __restrict__ wk, const float* __restrict__ bk,
           const float* __restrict__ wv, const float* __restrict__ bv) {
    const int mt = blockIdx.x, nt = blockIdx.y, which = blockIdx.z;
    const float* w    = (which == 0) ? wq : (which == 1) ? wk : wv;
    const float* bias = (which == 0) ? bq : (which == 1) ? bk : bv;

    float acc[4][4][4];
    #pragma unroll
    for (int i = 0; i < 4; ++i)
        #pragma unroll
        for (int j = 0; j < 4; ++j)
            #pragma unroll
            for (int r = 0; r < 4; ++r) acc[i][j][r] = 0.f;

    gemm_tile(x + (size_t)mt * 128 * IN_DIM, IN_DIM,
              w + (size_t)nt * 128 * IN_DIM, IN_DIM,
              IN_DIM / BK, acc);

    #pragma unroll
    for (int mi = 0; mi < 4; ++mi)
        #pragma unroll
        for (int ni = 0; ni < 4; ++ni) {
            int m0 = mt * 128 + frag_row(mi);
            int n  = nt * 128 + frag_col(ni);
            float b0 = __ldg(bias + n), b1 = __ldg(bias + n + 1);
            if (which == 2) {
                #pragma unroll
                for (int rr = 0; rr < 2; ++rr) {
                    int m = m0 + rr * 8;
                    int b = m >> 10, s = m & 1023;
                    g_vt[((size_t)b * OUT_DIM + n)     * SEQ + s] = acc[mi][ni][2*rr]     + b0;
                    g_vt[((size_t)b * OUT_DIM + n + 1) * SEQ + s] = acc[mi][ni][2*rr + 1] + b1;
                }
            } else {
                float* dst = which ? g_k : g_q;
                float2 v0 = make_float2(acc[mi][ni][0] + b0, acc[mi][ni][1] + b1);
                float2 v1 = make_float2(acc[mi][ni][2] + b0, acc[mi][ni][3] + b1);
                *reinterpret_cast<float2*>(&dst[(size_t)m0 * OUT_DIM + n])       = v0;
                *reinterpret_cast<float2*>(&dst[(size_t)(m0 + 8) * OUT_DIM + n]) = v1;
            }
        }
}

// ---------------------------------------------------------------------------
// Kernel 2: scores = (Q K^T) * SCALE per batch. grid (8, 8, 16).
// ---------------------------------------------------------------------------
__global__ void __launch_bounds__(THREADS, 1)
scores_kernel() {
    const int mt = blockIdx.x, nt = blockIdx.y, b = blockIdx.z;
    float acc[4][4][4];
    #pragma unroll
    for (int i = 0; i < 4; ++i)
        #pragma unroll
        for (int j = 0; j < 4; ++j)
            #pragma unroll
            for (int r = 0; r < 4; ++r) acc[i][j][r] = 0.f;

    gemm_tile(g_q + ((size_t)b * SEQ + mt * 128) * OUT_DIM, OUT_DIM,
              g_k + ((size_t)b * SEQ + nt * 128) * OUT_DIM, OUT_DIM,
              OUT_DIM / BK, acc);

    #pragma unroll
    for (int mi = 0; mi < 4; ++mi)
        #pragma unroll
        for (int ni = 0; ni < 4; ++ni) {
            int m0 = mt * 128 + frag_row(mi);
            int n  = nt * 128 + frag_col(ni);
            float* base = g_s + (size_t)b * SEQ * SEQ;
            float2 v0 = make_float2(acc[mi][ni][0] * SCALE, acc[mi][ni][1] * SCALE);
            float2 v1 = make_float2(acc[mi][ni][2] * SCALE, acc[mi][ni][3] * SCALE);
            *reinterpret_cast<float2*>(&base[(size_t)m0 * SEQ + n])       = v0;
            *reinterpret_cast<float2*>(&base[(size_t)(m0 + 8) * SEQ + n]) = v1;
        }
}

// ---------------------------------------------------------------------------
// Kernel 3: row softmax over g_s (in place). One 256-thread block per row.
// ---------------------------------------------------------------------------
__global__ void __launch_bounds__(THREADS)
softmax_kernel() {
    __shared__ float red[8];
    const size_t row = blockIdx.x;
    float4* p = reinterpret_cast<float4*>(g_s + row * SEQ);
    float4 v = p[threadIdx.x];

    float mx = fmaxf(fmaxf(v.x, v.y), fmaxf(v.z, v.w));
    #pragma unroll
    for (int o = 16; o > 0; o >>= 1)
        mx = fmaxf(mx, __shfl_xor_sync(0xFFFFFFFFu, mx, o));
    if ((threadIdx.x & 31) == 0) red[threadIdx.x >> 5] = mx;
    __syncthreads();
    float m2 = red[0];
    #pragma unroll
    for (int i = 1; i < 8; ++i) m2 = fmaxf(m2, red[i]);
    __syncthreads();

    v.x = __expf(v.x - m2);
    v.y = __expf(v.y - m2);
    v.z = __expf(v.z - m2);
    v.w = __expf(v.w - m2);
    float s = v.x + v.y + v.z + v.w;
    #pragma unroll
    for (int o = 16; o > 0; o >>= 1)
        s += __shfl_xor_sync(0xFFFFFFFFu, s, o);
    if ((threadIdx.x & 31) == 0) red[threadIdx.x >> 5] = s;
    __syncthreads();
    float tot = 0.f;
    #pragma unroll
    for (int i = 0; i < 8; ++i) tot += red[i];

    float inv = 1.0f / tot;
    v.x *= inv; v.y *= inv; v.z *= inv; v.w *= inv;
    p[threadIdx.x] = v;
}

// ---------------------------------------------------------------------------
// Kernel 4: out = P @ V. A = probs[1024,1024]; B = V^T[256,1024] per batch.
// grid (8 mtiles, 2 ntiles, 16 batches).
// ---------------------------------------------------------------------------
__global__ void __launch_bounds__(THREADS, 1)
pv_kernel(float* __restrict__ out) {
    const int mt = blockIdx.x, nt = blockIdx.y, b = blockIdx.z;
    float acc[4][4][4];
    #pragma unroll
    for (int i = 0; i < 4; ++i)
        #pragma unroll
        for (int j = 0; j < 4; ++j)
            #pragma unroll
            for (int r = 0; r < 4; ++r) acc[i][j][r] = 0.f;

    gemm_tile(g_s  + ((size_t)b * SEQ + mt * 128) * SEQ, SEQ,
              g_vt + ((size_t)b * OUT_DIM + nt * 128) * SEQ, SEQ,
              SEQ / BK, acc);

    #pragma unroll
    for (int mi = 0; mi < 4; ++mi)
        #pragma unroll
        for (int ni = 0; ni < 4; ++ni) {
            int m0 = mt * 128 + frag_row(mi);
            int n  = nt * 128 + frag_col(ni);
            float* base = out + (size_t)b * SEQ * OUT_DIM;
            float2 v0 = make_float2(acc[mi][ni][0], acc[mi][ni][1]);
            float2 v1 = make_float2(acc[mi][ni][2], acc[mi][ni][3]);
            *reinterpret_cast<float2*>(&base[(size_t)m0 * OUT_DIM + n])       = v0;
            *reinterpret_cast<float2*>(&base[(size_t)(m0 + 8) * OUT_DIM + n]) = v1;
        }
}

// ---------------------------------------------------------------------------
// Launcher
// ---------------------------------------------------------------------------
extern "C" void kernel_launch(void* const* d_in, const int* in_sizes, int n_in,
                              void* d_out, int out_size) {
    (void)in_sizes; (void)n_in; (void)out_size;
    const float* x  = (const float*)d_in[0];
    const float* wq = (const float*)d_in[1];
    const float* bq = (const float*)d_in[2];
    const float* wk = (const float*)d_in[3];
    const float* bk = (const float*)d_in[4];
    const float* wv = (const float*)d_in[5];
    const float* bv = (const float*)d_in[6];
    float* out = (float*)d_out;

    qkv_kernel<<<dim3(128, 2, 3), THREADS>>>(x, wq, bq, wk, bk, wv, bv);
    scores_kernel<<<dim3(8, 8, 16), THREADS>>>();
    softmax_kernel<<<BATCH * SEQ, THREADS>>>();
    pv_kernel<<<dim3(8, 2, 16), THREADS>>>(out);
}

// round 11
// speedup vs baseline: 1.3614x; 1.3614x over previous
#include <cuda_runtime.h>
#include <cuda_bf16.h>
#include <cstdint>

// ---------------------------------------------------------------------------
// Problem: B=16, S=1024, IN=512, OUT=256.
// out = softmax((x Wq^T)(x Wk^T)^T / sqrt(512)) (x Wv^T)
// RoPE uses ONE fixed rotation per dim-pair applied identically to Q and K;
// 2x2 rotations are orthogonal => (Rq).(Rk) = q.k, and V is unroped, so RoPE
// cancels exactly and is skipped.
//
// GEMM engine: mma.sync.m16n8k16 bf16 (family-portable HMMA; tcgen05 is not
// available on the sm_103 family target this harness compiles for).
// Accuracy: 2-term bf16 split (x = hi + lo): accumulate hh + hl + lh in fp32.
//
// R11: 2-stage SMEM double buffering, one __syncthreads per chunk. LDG for
// chunk+2 issued before the MMA block so DRAM latency hides behind tensor ops.
// ---------------------------------------------------------------------------
#define BATCH   16
#define SEQ     1024
#define IN_DIM  512
#define OUT_DIM 256

#define THREADS 256
#define BK 16              // fp32 elements per K-chunk

#define ROWB 48            // SMEM row stride bytes (16 bf16 = 32B + 16B pad)
#define TILE_HALF (128 * ROWB)       // one operand-half (hi or lo): 6144 B
#define STAGE_BYTES (4 * TILE_HALF)  // A_hi A_lo B_hi B_lo: 24576 B

#define SCALE 0.044194173824159216f  // 1/sqrt(512)

// ---------------------------------------------------------------------------
// Scratch (device globals; allocations are forbidden)
// ---------------------------------------------------------------------------
__device__ float g_q [BATCH * SEQ * OUT_DIM];          // [b*S+s][d]
__device__ float g_k [BATCH * SEQ * OUT_DIM];          // [b*S+s][d]
__device__ float g_vt[BATCH * OUT_DIM * SEQ];          // [b][d][s]  (V^T)
__device__ float g_s [(size_t)BATCH * SEQ * SEQ];      // scores/probs in place

// ---------------------------------------------------------------------------
// Helpers
// ---------------------------------------------------------------------------
__device__ __forceinline__ uint32_t smem_u32(const void* p) {
    uint32_t a;
    asm("{ .reg .u64 t; cvta.to.shared.u64 t, %1; cvt.u32.u64 %0, t; }"
        : "=r"(a) : "l"(p));
    return a;
}

#define LDSM4(R, addr) \
    asm volatile("ldmatrix.sync.aligned.m8n8.x4.shared.b16 {%0,%1,%2,%3}, [%4];" \
        : "=r"((R)[0]), "=r"((R)[1]), "=r"((R)[2]), "=r"((R)[3]) : "r"(addr))

#define MMA16816(C, A, B0, B1) \
    asm volatile( \
        "mma.sync.aligned.m16n8k16.row.col.f32.bf16.bf16.f32 " \
        "{%0,%1,%2,%3}, {%4,%5,%6,%7}, {%8,%9}, {%0,%1,%2,%3};" \
        : "+f"((C)[0]), "+f"((C)[1]), "+f"((C)[2]), "+f"((C)[3]) \
        : "r"((A)[0]), "r"((A)[1]), "r"((A)[2]), "r"((A)[3]), \
          "r"(B0), "r"(B1))

// ---------------------------------------------------------------------------
// Core tile GEMM: acc(128x128, fp32) += A[128 x K] @ B[128 x K]^T
// A, B fp32 row-major (K contiguous). Split-bf16 3-pass per chunk.
// Warp layout: 8 warps as 2(M) x 4(N); warp tile 64 x 32.
// 2-stage SMEM pipeline, one __syncthreads per chunk.
// ---------------------------------------------------------------------------
__device__ __forceinline__ void gemm_tile(const float* __restrict__ A, int lda,
                                          const float* __restrict__ B, int ldb,
                                          int nchunks, float (&acc)[4][4][4]) {
    __shared__ __align__(16) char smem[2 * STAGE_BYTES];   // 48 KB

    const int tid  = threadIdx.x;
    const int lane = tid & 31;
    const int warp = tid >> 5;
    const int wm = (warp >> 2) * 64;    // warp m origin (0 or 64)
    const int wn = (warp & 3) * 32;     // warp n origin (0,32,64,96)

    const uint32_t sb = smem_u32(smem);

    // ldmatrix addresses (stage 0 base; add stage offset when used).
    uint32_t a_addr[4];
    #pragma unroll
    for (int mi = 0; mi < 4; ++mi)
        a_addr[mi] = sb + (uint32_t)((wm + mi * 16 + (lane & 15)) * ROWB
                                     + (lane >> 4) * 16);
    uint32_t b_addr[2];
    #pragma unroll
    for (int p = 0; p < 2; ++p)
        b_addr[p] = sb + 2u * TILE_HALF
                  + (uint32_t)((wn + p * 16 + (lane & 7) + ((lane & 16) ? 8 : 0)) * ROWB
                               + ((lane & 8) ? 16 : 0));

    // Per-thread GMEM/SMEM coordinates for the fill (2 float4 per operand).
    const int r0 = tid >> 2,          f0 = tid & 3;
    const int r1 = (tid + 256) >> 2,  f1 = tid & 3;

    float4 pf[4];  // pf[0..1] = A float4s, pf[2..3] = B float4s

    auto load_pf = [&](int ch) {
        const float* An = A + (size_t)ch * BK;
        const float* Bn = B + (size_t)ch * BK;
        pf[0] = *reinterpret_cast<const float4*>(An + (size_t)r0 * lda + f0 * 4);
        pf[1] = *reinterpret_cast<const float4*>(An + (size_t)r1 * lda + f1 * 4);
        pf[2] = *reinterpret_cast<const float4*>(Bn + (size_t)r0 * ldb + f0 * 4);
        pf[3] = *reinterpret_cast<const float4*>(Bn + (size_t)r1 * ldb + f1 * 4);
    };

    auto store_pf = [&](int st) {
        char* base = smem + st * STAGE_BYTES;
        #pragma unroll
        for (int i = 0; i < 4; ++i) {
            int r = (i & 1) ? r1 : r0;
            int f = f0;
            char* dst = base + (i < 2 ? 0 : 2 * TILE_HALF) + r * ROWB + f * 8;
            float4 v = pf[i];
            __nv_bfloat162 h0 = __floats2bfloat162_rn(v.x, v.y);
            __nv_bfloat162 h1 = __floats2bfloat162_rn(v.z, v.w);
            float2 q0 = __bfloat1622float2(h0);
            float2 q1 = __bfloat1622float2(h1);
            __nv_bfloat162 l0 = __floats2bfloat162_rn(v.x - q0.x, v.y - q0.y);
            __nv_bfloat162 l1 = __floats2bfloat162_rn(v.z - q1.x, v.w - q1.y);
            uint2 hw = make_uint2(*reinterpret_cast<uint32_t*>(&h0),
                                  *reinterpret_cast<uint32_t*>(&h1));
            uint2 lw = make_uint2(*reinterpret_cast<uint32_t*>(&l0),
                                  *reinterpret_cast<uint32_t*>(&l1));
            *reinterpret_cast<uint2*>(dst) = hw;
            *reinterpret_cast<uint2*>(dst + TILE_HALF) = lw;
        }
    };

    // Prologue: stage 0 filled with chunk 0; chunk 1 in flight in registers.
    load_pf(0);
    store_pf(0);
    if (nchunks > 1) load_pf(1);
    __syncthreads();

    #pragma unroll 1
    for (int ch = 0; ch < nchunks; ++ch) {
        const int st = ch & 1;
        const uint32_t soff = (uint32_t)st * STAGE_BYTES;

        // 1) Fragments for this chunk from stage st.
        uint32_t ah[4][4], al[4][4], bh[4][2], bl[4][2];
        #pragma unroll
        for (int mi = 0; mi < 4; ++mi) {
            LDSM4(ah[mi], a_addr[mi] + soff);
            LDSM4(al[mi], a_addr[mi] + soff + TILE_HALF);
        }
        #pragma unroll
        for (int p = 0; p < 2; ++p) {
            uint32_t t[4];
            LDSM4(t, b_addr[p] + soff);
            bh[2*p][0] = t[0]; bh[2*p][1] = t[1];
            bh[2*p+1][0] = t[2]; bh[2*p+1][1] = t[3];
            LDSM4(t, b_addr[p] + soff + TILE_HALF);
            bl[2*p][0] = t[0]; bl[2*p][1] = t[1];
            bl[2*p+1][0] = t[2]; bl[2*p+1][1] = t[3];
        }

        // 2) Convert chunk ch+1 into the other stage (frees pf).
        if (ch + 1 < nchunks) store_pf(st ^ 1);

        // 3) Issue chunk ch+2 LDGs; they drain behind the MMA block.
        if (ch + 2 < nchunks) load_pf(ch + 2);

        // 4) 3-pass split MMA: hh + hl + lh.
        #pragma unroll
        for (int mi = 0; mi < 4; ++mi)
            #pragma unroll
            for (int ni = 0; ni < 4; ++ni) {
                MMA16816(acc[mi][ni], ah[mi], bh[ni][0], bh[ni][1]);
                MMA16816(acc[mi][ni], ah[mi], bl[ni][0], bl[ni][1]);
                MMA16816(acc[mi][ni], al[mi], bh[ni][0], bh[ni][1]);
            }

        // 5) Make the stage-(st^1) stores visible; also ensures all warps are
        //    done with stage st before it is overwritten two iterations later.
        __syncthreads();
    }
}

// Fragment -> (row, col) helpers. C regs: r0,r1 at (row, col..col+1),
// r2,r3 at (row+8, col..col+1).
__device__ __forceinline__ int frag_row(int mi) {
    int lane = threadIdx.x & 31, warp = threadIdx.x >> 5;
    return (warp >> 2) * 64 + mi * 16 + (lane >> 2);
}
__device__ __forceinline__ int frag_col(int ni) {
    int lane = threadIdx.x & 31, warp = threadIdx.x >> 5;
    return (warp & 3) * 32 + ni * 8 + 2 * (lane & 3);
}

// ---------------------------------------------------------------------------
// Kernel 1: fused QKV. A = x[16384,512]; B = W[256,512] (rows = out dim).
// grid (128 mtiles, 2 ntiles, 3 which). which: 0=Q, 1=K, 2=V (stored V^T).
// ---------------------------------------------------------------------------
__global__ void __launch_bounds__(THREADS, 1)
qkv_kernel(const float* __restrict__ x,
           const float* __restrict__ wq, const float* __restrict__ bq,
           const float* __restrict__ wk, const float* __restrict__ bk,
           const float* __restrict__ wv, const float* __restrict__ bv) {
    const int mt = blockIdx.x, nt = blockIdx.y, which = blockIdx.z;
    const float* w    = (which == 0) ? wq : (which == 1) ? wk : wv;
    const float* bias = (which == 0) ? bq : (which == 1) ? bk : bv;

    float acc[4][4][4];
    #pragma unroll
    for (int i = 0; i < 4; ++i)
        #pragma unroll
        for (int j = 0; j < 4; ++j)
            #pragma unroll
            for (int r = 0; r < 4; ++r) acc[i][j][r] = 0.f;

    gemm_tile(x + (size_t)mt * 128 * IN_DIM, IN_DIM,
              w + (size_t)nt * 128 * IN_DIM, IN_DIM,
              IN_DIM / BK, acc);

    #pragma unroll
    for (int mi = 0; mi < 4; ++mi)
        #pragma unroll
        for (int ni = 0; ni < 4; ++ni) {
            int m0 = mt * 128 + frag_row(mi);
            int n  = nt * 128 + frag_col(ni);
            float b0 = __ldg(bias + n), b1 = __ldg(bias + n + 1);
            if (which == 2) {
                #pragma unroll
                for (int rr = 0; rr < 2; ++rr) {
                    int m = m0 + rr * 8;
                    int b = m >> 10, s = m & 1023;
                    g_vt[((size_t)b * OUT_DIM + n)     * SEQ + s] = acc[mi][ni][2*rr]     + b0;
                    g_vt[((size_t)b * OUT_DIM + n + 1) * SEQ + s] = acc[mi][ni][2*rr + 1] + b1;
                }
            } else {
                float* dst = which ? g_k : g_q;
                float2 v0 = make_float2(acc[mi][ni][0] + b0, acc[mi][ni][1] + b1);
                float2 v1 = make_float2(acc[mi][ni][2] + b0, acc[mi][ni][3] + b1);
                *reinterpret_cast<float2*>(&dst[(size_t)m0 * OUT_DIM + n])       = v0;
                *reinterpret_cast<float2*>(&dst[(size_t)(m0 + 8) * OUT_DIM + n]) = v1;
            }
        }
}

// ---------------------------------------------------------------------------
// Kernel 2: scores = (Q K^T) * SCALE per batch. grid (8, 8, 16).
// ---------------------------------------------------------------------------
__global__ void __launch_bounds__(THREADS, 1)
scores_kernel() {
    const int mt = blockIdx.x, nt = blockIdx.y, b = blockIdx.z;
    float acc[4][4][4];
    #pragma unroll
    for (int i = 0; i < 4; ++i)
        #pragma unroll
        for (int j = 0; j < 4; ++j)
            #pragma unroll
            for (int r = 0; r < 4; ++r) acc[i][j][r] = 0.f;

    gemm_tile(g_q + ((size_t)b * SEQ + mt * 128) * OUT_DIM, OUT_DIM,
              g_k + ((size_t)b * SEQ + nt * 128) * OUT_DIM, OUT_DIM,
              OUT_DIM / BK, acc);

    #pragma unroll
    for (int mi = 0; mi < 4; ++mi)
        #pragma unroll
        for (int ni = 0; ni < 4; ++ni) {
            int m0 = mt * 128 + frag_row(mi);
            int n  = nt * 128 + frag_col(ni);
            float* base = g_s + (size_t)b * SEQ * SEQ;
            float2 v0 = make_float2(acc[mi][ni][0] * SCALE, acc[mi][ni][1] * SCALE);
            float2 v1 = make_float2(acc[mi][ni][2] * SCALE, acc[mi][ni][3] * SCALE);
            *reinterpret_cast<float2*>(&base[(size_t)m0 * SEQ + n])       = v0;
            *reinterpret_cast<float2*>(&base[(size_t)(m0 + 8) * SEQ + n]) = v1;
        }
}

// ---------------------------------------------------------------------------
// Kernel 3: row softmax over g_s (in place). One 256-thread block per row.
// ---------------------------------------------------------------------------
__global__ void __launch_bounds__(THREADS)
softmax_kernel() {
    __shared__ float red[8];
    const size_t row = blockIdx.x;
    float4* p = reinterpret_cast<float4*>(g_s + row * SEQ);
    float4 v = p[threadIdx.x];

    float mx = fmaxf(fmaxf(v.x, v.y), fmaxf(v.z, v.w));
    #pragma unroll
    for (int o = 16; o > 0; o >>= 1)
        mx = fmaxf(mx, __shfl_xor_sync(0xFFFFFFFFu, mx, o));
    if ((threadIdx.x & 31) == 0) red[threadIdx.x >> 5] = mx;
    __syncthreads();
    float m2 = red[0];
    #pragma unroll
    for (int i = 1; i < 8; ++i) m2 = fmaxf(m2, red[i]);
    __syncthreads();

    v.x = __expf(v.x - m2);
    v.y = __expf(v.y - m2);
    v.z = __expf(v.z - m2);
    v.w = __expf(v.w - m2);
    float s = v.x + v.y + v.z + v.w;
    #pragma unroll
    for (int o = 16; o > 0; o >>= 1)
        s += __shfl_xor_sync(0xFFFFFFFFu, s, o);
    if ((threadIdx.x & 31) == 0) red[threadIdx.x >> 5] = s;
    __syncthreads();
    float tot = 0.f;
    #pragma unroll
    for (int i = 0; i < 8; ++i) tot += red[i];

    float inv = 1.0f / tot;
    v.x *= inv; v.y *= inv; v.z *= inv; v.w *= inv;
    p[threadIdx.x] = v;
}

// ---------------------------------------------------------------------------
// Kernel 4: out = P @ V. A = probs[1024,1024]; B = V^T[256,1024] per batch.
// grid (8 mtiles, 2 ntiles, 16 batches).
// ---------------------------------------------------------------------------
__global__ void __launch_bounds__(THREADS, 1)
pv_kernel(float* __restrict__ out) {
    const int mt = blockIdx.x, nt = blockIdx.y, b = blockIdx.z;
    float acc[4][4][4];
    #pragma unroll
    for (int i = 0; i < 4; ++i)
        #pragma unroll
        for (int j = 0; j < 4; ++j)
            #pragma unroll
            for (int r = 0; r < 4; ++r) acc[i][j][r] = 0.f;

    gemm_tile(g_s  + ((size_t)b * SEQ + mt * 128) * SEQ, SEQ,
              g_vt + ((size_t)b * OUT_DIM + nt * 128) * SEQ, SEQ,
              SEQ / BK, acc);

    #pragma unroll
    for (int mi = 0; mi < 4; ++mi)
        #pragma unroll
        for (int ni = 0; ni < 4; ++ni) {
            int m0 = mt * 128 + frag_row(mi);
            int n  = nt * 128 + frag_col(ni);
            float* base = out + (size_t)b * SEQ * OUT_DIM;
            float2 v0 = make_float2(acc[mi][ni][0], acc[mi][ni][1]);
            float2 v1 = make_float2(acc[mi][ni][2], acc[mi][ni][3]);
            *reinterpret_cast<float2*>(&base[(size_t)m0 * OUT_DIM + n])       = v0;
            *reinterpret_cast<float2*>(&base[(size_t)(m0 + 8) * OUT_DIM + n]) = v1;
        }
}

// ---------------------------------------------------------------------------
// Launcher
// ---------------------------------------------------------------------------
extern "C" void kernel_launch(void* const* d_in, const int* in_sizes, int n_in,
                              void* d_out, int out_size) {
    (void)in_sizes; (void)n_in; (void)out_size;
    const float* x  = (const float*)d_in[0];
    const float* wq = (const float*)d_in[1];
    const float* bq = (const float*)d_in[2];
    const float* wk = (const float*)d_in[3];
    const float* bk = (const float*)d_in[4];
    const float* wv = (const float*)d_in[5];
    const float* bv = (const float*)d_in[6];
    float* out = (float*)d_out;

    qkv_kernel<<<dim3(128, 2, 3), THREADS>>>(x, wq, bq, wk, bk, wv, bv);
    scores_kernel<<<dim3(8, 8, 16), THREADS>>>();
    softmax_kernel<<<BATCH * SEQ, THREADS>>>();
    pv_kernel<<<dim3(8, 2, 16), THREADS>>>(out);
}